// round 8
// baseline (speedup 1.0000x reference)
#include <cuda_runtime.h>
#include <cuda_fp16.h>
#include <cstdint>
#include <math.h>

// Problem constants
#define T_TOK 4096
#define D_DIM 2048
#define FF_DIM 8192
#define E_EXP 16
#define CAP 640          // ceil(1.25 * 2 * 4096 / 16)

// ---------------------------------------------------------------------------
// Scratch (device globals — allocation-free kernel_launch)
// ---------------------------------------------------------------------------
__device__ __half g_W1h[(size_t)E_EXP * D_DIM * FF_DIM];  // W1 fp16 [E][D][FF]
__device__ __half g_W2h[(size_t)E_EXP * FF_DIM * D_DIM];  // W2 fp16 [E][FF][D]
__device__ __half g_Xe [(size_t)E_EXP * CAP * D_DIM];     // dispatched tokens fp16
__device__ __half g_h  [(size_t)E_EXP * CAP * FF_DIM];    // gelu(Xe@W1+b1) fp16
__device__ __half g_Ye [(size_t)E_EXP * CAP * D_DIM];     // expert outputs fp16
__device__ int    g_eidx[T_TOK * 2];
__device__ float  g_gate[T_TOK * 2];
__device__ int    g_pos [T_TOK * 2];

// ---------------------------------------------------------------------------
// Helpers
// ---------------------------------------------------------------------------
__device__ __forceinline__ float gelu_exact(float v) {
    return 0.5f * v * (1.0f + erff(v * 0.70710678118654752f));
}

__device__ __forceinline__ void cp_async16(uint32_t smem_addr, const void* gmem) {
    asm volatile("cp.async.cg.shared.global [%0], [%1], 16;\n" :: "r"(smem_addr), "l"(gmem));
}

__device__ __forceinline__ void ldsm_x4(uint32_t (&r)[4], uint32_t addr) {
    asm volatile("ldmatrix.sync.aligned.m8n8.x4.shared.b16 {%0,%1,%2,%3}, [%4];"
        : "=r"(r[0]), "=r"(r[1]), "=r"(r[2]), "=r"(r[3]) : "r"(addr));
}

__device__ __forceinline__ void ldsm_x4_trans(uint32_t (&r)[4], uint32_t addr) {
    asm volatile("ldmatrix.sync.aligned.m8n8.x4.trans.shared.b16 {%0,%1,%2,%3}, [%4];"
        : "=r"(r[0]), "=r"(r[1]), "=r"(r[2]), "=r"(r[3]) : "r"(addr));
}

__device__ __forceinline__ void mma_f16(float (&c)[4], const uint32_t (&a)[4],
                                        uint32_t b0, uint32_t b1) {
    asm volatile(
        "mma.sync.aligned.m16n8k16.row.col.f32.f16.f16.f32 "
        "{%0,%1,%2,%3}, {%4,%5,%6,%7}, {%8,%9}, {%0,%1,%2,%3};"
        : "+f"(c[0]), "+f"(c[1]), "+f"(c[2]), "+f"(c[3])
        : "r"(a[0]), "r"(a[1]), "r"(a[2]), "r"(a[3]), "r"(b0), "r"(b1));
}

// ---------------------------------------------------------------------------
// 1) Gating: one warp per token (unchanged, proven)
// ---------------------------------------------------------------------------
__global__ void gate_kernel(const float* __restrict__ x, const float* __restrict__ Wg) {
    int t = (blockIdx.x * blockDim.x + threadIdx.x) >> 5;
    int lane = threadIdx.x & 31;
    if (t >= T_TOK) return;
    const float* xr = x + (size_t)t * D_DIM;

    float acc[E_EXP];
#pragma unroll
    for (int e = 0; e < E_EXP; e++) acc[e] = 0.0f;

    for (int d = lane; d < D_DIM; d += 32) {
        float xv = xr[d];
        const float4* wg = (const float4*)(Wg + (size_t)d * E_EXP);
#pragma unroll
        for (int q = 0; q < 4; q++) {
            float4 w = wg[q];
            acc[q * 4 + 0] += xv * w.x;
            acc[q * 4 + 1] += xv * w.y;
            acc[q * 4 + 2] += xv * w.z;
            acc[q * 4 + 3] += xv * w.w;
        }
    }
#pragma unroll
    for (int e = 0; e < E_EXP; e++) {
        float v = acc[e];
#pragma unroll
        for (int o = 16; o > 0; o >>= 1) v += __shfl_xor_sync(0xffffffffu, v, o);
        acc[e] = v;
    }
    if (lane == 0) {
        int i1 = 0; float v1 = acc[0];
#pragma unroll
        for (int e = 1; e < E_EXP; e++) if (acc[e] > v1) { v1 = acc[e]; i1 = e; }
        int i2 = -1; float v2 = -1e30f;
#pragma unroll
        for (int e = 0; e < E_EXP; e++)
            if (e != i1 && acc[e] > v2) { v2 = acc[e]; i2 = e; }
        float r  = expf(v2 - v1);
        float g1 = 1.0f / (1.0f + r);
        float g2 = r * g1;
        g_eidx[t * 2 + 0] = i1;  g_eidx[t * 2 + 1] = i2;
        g_gate[t * 2 + 0] = g1;  g_gate[t * 2 + 1] = g2;
    }
}

// ---------------------------------------------------------------------------
// 2) Ordered capacity scan — PARALLEL (proven in R7)
// ---------------------------------------------------------------------------
__global__ void scan_kernel() {
    const int e = blockIdx.x;
    const int wid = threadIdx.x >> 5, lane = threadIdx.x & 31;
    __shared__ int wcnt[8], wbase[8];
    __shared__ int carry;
    if (threadIdx.x == 0) carry = 0;
    __syncthreads();

#pragma unroll
    for (int s = 0; s < 2; s++) {
        int cnt = 0;
        for (int t0 = wid * 512; t0 < wid * 512 + 512; t0 += 32) {
            bool m = (g_eidx[(t0 + lane) * 2 + s] == e);
            cnt += __popc(__ballot_sync(0xffffffffu, m));
        }
        if (lane == 0) wcnt[wid] = cnt;
        __syncthreads();
        if (threadIdx.x == 0) {
            int r = carry;
#pragma unroll
            for (int w = 0; w < 8; w++) { wbase[w] = r; r += wcnt[w]; }
            carry = r;
        }
        __syncthreads();
        int off = wbase[wid];
        for (int t0 = wid * 512; t0 < wid * 512 + 512; t0 += 32) {
            int t = t0 + lane;
            bool m = (g_eidx[t * 2 + s] == e);
            unsigned mask = __ballot_sync(0xffffffffu, m);
            if (m) g_pos[t * 2 + s] = off + __popc(mask & ((1u << lane) - 1u));
            off += __popc(mask);
        }
        __syncthreads();
    }
}

// ---------------------------------------------------------------------------
// 3) Dispatch: scatter token rows into Xe as fp16 (no memset needed)
// ---------------------------------------------------------------------------
__global__ void dispatch_kernel(const float* __restrict__ x) {
    int t = blockIdx.x;
    const float4* xr = (const float4*)(x + (size_t)t * D_DIM);
#pragma unroll
    for (int k = 0; k < 2; k++) {
        int p = g_pos[t * 2 + k];
        if (p < CAP) {
            int e = g_eidx[t * 2 + k];
            uint2* dst = (uint2*)(g_Xe + ((size_t)e * CAP + p) * D_DIM);
            for (int i = threadIdx.x; i < D_DIM / 4; i += blockDim.x) {
                float4 v = xr[i];
                __half2 a = __floats2half2_rn(v.x, v.y);
                __half2 b = __floats2half2_rn(v.z, v.w);
                uint2 u;
                u.x = *reinterpret_cast<uint32_t*>(&a);
                u.y = *reinterpret_cast<uint32_t*>(&b);
                dst[i] = u;
            }
        }
    }
}

// ---------------------------------------------------------------------------
// 3b) Weight convert fp32 -> fp16, layout preserved
// ---------------------------------------------------------------------------
__global__ void convert_w(const float4* __restrict__ in, uint2* __restrict__ out) {
    size_t i = (size_t)blockIdx.x * blockDim.x + threadIdx.x;
    float4 v = in[i];
    __half2 a = __floats2half2_rn(v.x, v.y);
    __half2 b = __floats2half2_rn(v.z, v.w);
    uint2 u;
    u.x = *reinterpret_cast<uint32_t*>(&a);
    u.y = *reinterpret_cast<uint32_t*>(&b);
    out[i] = u;
}

// ---------------------------------------------------------------------------
// 4) Grouped GEMM, fp16 mma.sync.m16n8k16 + ldmatrix, fp32 accumulate.
//    Parameterized tile height:
//      BM=320, 512 thr: 16 warps (4M x 4N), warp 80x32, 1 CTA/SM  (GEMM1)
//      BM=128, 256 thr:  8 warps (2M x 4N), warp 64x32, 2 CTA/SM  (GEMM2)
//    BN=128, BK=64, 3-stage cp.async ring. A rows 72 halves (144B), B rows
//    136 halves (272B) => conflict-free ldmatrix. Smem-staged epilogue.
// ---------------------------------------------------------------------------
#define BK 64
#define SA 72            // halves per A smem row (144 B)
#define SB 136           // halves per B smem row (272 B)

template<int BM, int THREADS, int KDIM, int NDIM, bool DOGELU, bool HALFOUT>
__global__ void __launch_bounds__(THREADS, (THREADS == 256) ? 2 : 1)
gemm_hmma(const __half* __restrict__ A, const __half* __restrict__ Bw,
          const float* __restrict__ bias, void* __restrict__ Cout) {
    constexpr int KT = KDIM / BK;
    constexpr int WMCNT = THREADS / 32 / 4;       // warps along M
    constexpr int FM = BM / (WMCNT * 16);         // 16-row fragments per warp
    constexpr int A_BYTES = BM * SA * 2;
    constexpr int B_BYTES = BK * SB * 2;
    constexpr int STAGE_BYTES = A_BYTES + B_BYTES;
    constexpr int NA = BM * 8 / THREADS;          // A cp.async slots per thread
    constexpr int NB = BK * 16 / THREADS;         // B cp.async slots per thread

    extern __shared__ char smem[];
    const uint32_t smem_u32 = (uint32_t)__cvta_generic_to_shared(smem);
    const int tid = threadIdx.x, lane = tid & 31, wid = tid >> 5;
    const int mt = blockIdx.x, nt = blockIdx.y, e = blockIdx.z;
    const int wm = (wid % WMCNT) * (FM * 16), wn = (wid / WMCNT) * 32;

    const __half* Ae = A  + ((size_t)e * CAP + (size_t)mt * BM) * KDIM;
    const __half* Be = Bw + (size_t)e * KDIM * NDIM + (size_t)nt * 128;

    // cp.async slots: 32-bit element offsets to save registers
    uint32_t sAoff[NA], gAoff[NA], sBoff[NB], gBoff[NB];
#pragma unroll
    for (int i = 0; i < NA; i++) {
        int u = tid + i * THREADS;
        int ar = u >> 3, ac = (u & 7) * 8;        // A: BM rows x 8 chunks of 8 halves
        sAoff[i] = (ar * SA + ac) * 2;
        gAoff[i] = (uint32_t)ar * KDIM + ac;
    }
#pragma unroll
    for (int i = 0; i < NB; i++) {
        int u = tid + i * THREADS;
        int br = u >> 4, bc = (u & 15) * 8;       // B: 64 rows x 16 chunks
        sBoff[i] = (uint32_t)A_BYTES + (br * SB + bc) * 2;
        gBoff[i] = (uint32_t)br * NDIM + bc;
    }

    // ldmatrix base offsets (bytes, within a stage)
    uint32_t aoff[FM], boff[2];
#pragma unroll
    for (int fm = 0; fm < FM; fm++) {
        int row = wm + fm * 16 + (lane & 15);
        int kc  = (lane >> 4) * 8;
        aoff[fm] = (row * SA + kc) * 2;
    }
#pragma unroll
    for (int png = 0; png < 2; png++) {
        int kr = lane & 15;
        int nc = wn + png * 16 + (lane >> 4) * 8;
        boff[png] = (uint32_t)A_BYTES + (kr * SB + nc) * 2;
    }

    float acc[FM][4][4];
#pragma unroll
    for (int i = 0; i < FM; i++)
#pragma unroll
        for (int j = 0; j < 4; j++)
#pragma unroll
            for (int q = 0; q < 4; q++) acc[i][j][q] = 0.0f;

    auto load_stage = [&](int s, int kt) {
        uint32_t sb = smem_u32 + s * STAGE_BYTES;
#pragma unroll
        for (int i = 0; i < NA; i++) cp_async16(sb + sAoff[i], Ae + gAoff[i] + kt * BK);
#pragma unroll
        for (int i = 0; i < NB; i++)
            cp_async16(sb + sBoff[i], Be + gBoff[i] + (uint32_t)kt * BK * NDIM);
        asm volatile("cp.async.commit_group;" ::: "memory");
    };

    load_stage(0, 0);
    load_stage(1, 1);

    int s_cur = 0, s_nxt = 2;
    for (int kt = 0; kt < KT; kt++) {
        if (kt + 2 < KT) asm volatile("cp.async.wait_group 1;" ::: "memory");
        else             asm volatile("cp.async.wait_group 0;" ::: "memory");
        __syncthreads();
        if (kt + 2 < KT) load_stage(s_nxt, kt + 2);

        uint32_t sb = smem_u32 + s_cur * STAGE_BYTES;
#pragma unroll
        for (int ks = 0; ks < 4; ks++) {
            uint32_t a[FM][4], b[2][4];
#pragma unroll
            for (int fm = 0; fm < FM; fm++)
                ldsm_x4(a[fm], sb + aoff[fm] + ks * 32);            // +16 halves in k
#pragma unroll
            for (int png = 0; png < 2; png++)
                ldsm_x4_trans(b[png], sb + boff[png] + ks * (16 * SB * 2));
#pragma unroll
            for (int fm = 0; fm < FM; fm++)
#pragma unroll
                for (int fn = 0; fn < 4; fn++)
                    mma_f16(acc[fm][fn], a[fm], b[fn >> 1][(fn & 1) * 2],
                            b[fn >> 1][(fn & 1) * 2 + 1]);
        }
        s_cur = (s_cur == 2) ? 0 : s_cur + 1;
        s_nxt = (s_nxt == 2) ? 0 : s_nxt + 1;
    }

    // bias for this warp's columns
    float bias0[4], bias1[4];
#pragma unroll
    for (int fn = 0; fn < 4; fn++) {
        int c = nt * 128 + wn + fn * 8 + (lane & 3) * 2;
        bias0[fn] = __ldg(bias + (size_t)e * NDIM + c);
        bias1[fn] = __ldg(bias + (size_t)e * NDIM + c + 1);
    }

    __syncthreads();   // mainloop smem dead -> reuse as epilogue staging

    if (HALFOUT) {
        __half* buf = (__half*)smem;          // [BM][136] halves
#pragma unroll
        for (int fm = 0; fm < FM; fm++) {
#pragma unroll
            for (int fn = 0; fn < 4; fn++) {
                int row = wm + fm * 16 + (lane >> 2);
                int col = wn + fn * 8 + (lane & 3) * 2;
                float v0 = acc[fm][fn][0] + bias0[fn];
                float v1 = acc[fm][fn][1] + bias1[fn];
                float v2 = acc[fm][fn][2] + bias0[fn];
                float v3 = acc[fm][fn][3] + bias1[fn];
                if (DOGELU) {
                    v0 = gelu_exact(v0); v1 = gelu_exact(v1);
                    v2 = gelu_exact(v2); v3 = gelu_exact(v3);
                }
                __half2 p0 = __floats2half2_rn(v0, v1);
                __half2 p1 = __floats2half2_rn(v2, v3);
                *(uint32_t*)(buf + row * 136 + col)       = *reinterpret_cast<uint32_t*>(&p0);
                *(uint32_t*)(buf + (row + 8) * 136 + col) = *reinterpret_cast<uint32_t*>(&p1);
            }
        }
        __syncthreads();
        __half* Ce = (__half*)Cout + ((size_t)e * CAP + (size_t)mt * BM) * NDIM
                   + (size_t)nt * 128;
#pragma unroll
        for (int i = tid; i < BM * 16; i += THREADS) {   // BM rows x 16 uint4
            int rr = i >> 4, cc = i & 15;
            uint4 v = *(const uint4*)(buf + rr * 136 + cc * 8);
            *(uint4*)(Ce + (size_t)rr * NDIM + cc * 8) = v;
        }
    } else {
        float* buf = (float*)smem;            // [BM][132] floats
#pragma unroll
        for (int fm = 0; fm < FM; fm++) {
#pragma unroll
            for (int fn = 0; fn < 4; fn++) {
                int row = wm + fm * 16 + (lane >> 2);
                int col = wn + fn * 8 + (lane & 3) * 2;
                float v0 = acc[fm][fn][0] + bias0[fn];
                float v1 = acc[fm][fn][1] + bias1[fn];
                float v2 = acc[fm][fn][2] + bias0[fn];
                float v3 = acc[fm][fn][3] + bias1[fn];
                *(float2*)(buf + row * 132 + col)       = make_float2(v0, v1);
                *(float2*)(buf + (row + 8) * 132 + col) = make_float2(v2, v3);
            }
        }
        __syncthreads();
        float* Ce = (float*)Cout + ((size_t)e * CAP + (size_t)mt * BM) * NDIM
                  + (size_t)nt * 128;
#pragma unroll
        for (int i = tid; i < BM * 32; i += THREADS) {   // BM rows x 32 uint4
            int rr = i >> 5, cc = i & 31;
            uint4 v = *(const uint4*)(buf + rr * 132 + cc * 4);
            *(uint4*)(Ce + (size_t)rr * NDIM + cc * 4) = v;
        }
    }
}

#define SMEM_G1 (3 * (320 * SA * 2 + BK * SB * 2))   // 190464
#define SMEM_G2 (3 * (128 * SA * 2 + BK * SB * 2))   // 107520

// ---------------------------------------------------------------------------
// 5) Combine: Ye is fp16 now
// ---------------------------------------------------------------------------
__global__ void combine_kernel(float* __restrict__ out) {
    int t = blockIdx.x;
    int e0 = g_eidx[t * 2 + 0], e1 = g_eidx[t * 2 + 1];
    int p0 = g_pos[t * 2 + 0],  p1 = g_pos[t * 2 + 1];
    float g0 = (p0 < CAP) ? g_gate[t * 2 + 0] : 0.0f;
    float g1 = (p1 < CAP) ? g_gate[t * 2 + 1] : 0.0f;
    p0 = min(p0, CAP - 1);
    p1 = min(p1, CAP - 1);
    const uint2* y0 = (const uint2*)(g_Ye + ((size_t)e0 * CAP + p0) * D_DIM);
    const uint2* y1 = (const uint2*)(g_Ye + ((size_t)e1 * CAP + p1) * D_DIM);
    float4* o = (float4*)(out + (size_t)t * D_DIM);
    for (int i = threadIdx.x; i < D_DIM / 4; i += blockDim.x) {
        uint2 ua = y0[i], ub = y1[i];
        float2 a0 = __half22float2(*reinterpret_cast<__half2*>(&ua.x));
        float2 a1 = __half22float2(*reinterpret_cast<__half2*>(&ua.y));
        float2 b0 = __half22float2(*reinterpret_cast<__half2*>(&ub.x));
        float2 b1 = __half22float2(*reinterpret_cast<__half2*>(&ub.y));
        float4 rv;
        rv.x = g0 * a0.x + g1 * b0.x;
        rv.y = g0 * a0.y + g1 * b0.y;
        rv.z = g0 * a1.x + g1 * b1.x;
        rv.w = g0 * a1.y + g1 * b1.y;
        o[i] = rv;
    }
}

// ---------------------------------------------------------------------------
// kernel_launch — R7 structure: converts forked on s2; monolithic GEMMs.
// ---------------------------------------------------------------------------
extern "C" void kernel_launch(void* const* d_in, const int* in_sizes, int n_in,
                              void* d_out, int out_size) {
    const float* x  = (const float*)d_in[0];
    const float* Wg = (const float*)d_in[1];
    const float* W1 = (const float*)d_in[2];
    const float* b1 = (const float*)d_in[3];
    const float* W2 = (const float*)d_in[4];
    const float* b2 = (const float*)d_in[5];
    float* out = (float*)d_out;

    void *xe_p, *h_p, *ye_p, *w1_p, *w2_p;
    cudaGetSymbolAddress(&xe_p, g_Xe);
    cudaGetSymbolAddress(&h_p,  g_h);
    cudaGetSymbolAddress(&ye_p, g_Ye);
    cudaGetSymbolAddress(&w1_p, g_W1h);
    cudaGetSymbolAddress(&w2_p, g_W2h);

    static cudaStream_t s2 = [] {
        cudaStream_t s;
        cudaStreamCreateWithFlags(&s, cudaStreamNonBlocking);
        return s;
    }();
    static cudaEvent_t evStart = [] {
        cudaEvent_t e; cudaEventCreateWithFlags(&e, cudaEventDisableTiming); return e;
    }();
    static cudaEvent_t evW1 = [] {
        cudaEvent_t e; cudaEventCreateWithFlags(&e, cudaEventDisableTiming); return e;
    }();
    static cudaEvent_t evW2 = [] {
        cudaEvent_t e; cudaEventCreateWithFlags(&e, cudaEventDisableTiming); return e;
    }();

    cudaFuncSetAttribute(gemm_hmma<320, 512, D_DIM, FF_DIM, true,  true>,
                         cudaFuncAttributeMaxDynamicSharedMemorySize, SMEM_G1);
    cudaFuncSetAttribute(gemm_hmma<128, 256, FF_DIM, D_DIM, false, true>,
                         cudaFuncAttributeMaxDynamicSharedMemorySize, SMEM_G2);

    // fork: weight conversion on s2
    cudaEventRecord(evStart, 0);
    cudaStreamWaitEvent(s2, evStart, 0);
    const size_t WN = (size_t)E_EXP * D_DIM * FF_DIM;   // elements per weight tensor
    convert_w<<<(unsigned)(WN / 4 / 256), 256, 0, s2>>>((const float4*)W1, (uint2*)w1_p);
    cudaEventRecord(evW1, s2);
    convert_w<<<(unsigned)(WN / 4 / 256), 256, 0, s2>>>((const float4*)W2, (uint2*)w2_p);
    cudaEventRecord(evW2, s2);

    // main stream: gating chain
    gate_kernel<<<T_TOK / 8, 256>>>(x, Wg);
    scan_kernel<<<E_EXP, 256>>>();
    dispatch_kernel<<<T_TOK, 256>>>(x);

    cudaStreamWaitEvent(0, evW1, 0);
    gemm_hmma<320, 512, D_DIM, FF_DIM, true, true>
        <<<dim3(CAP / 320, FF_DIM / 128, E_EXP), 512, SMEM_G1>>>(
        (const __half*)xe_p, (const __half*)w1_p, b1, h_p);

    cudaStreamWaitEvent(0, evW2, 0);
    gemm_hmma<128, 256, FF_DIM, D_DIM, false, true>
        <<<dim3(CAP / 128, D_DIM / 128, E_EXP), 256, SMEM_G2>>>(
        (const __half*)h_p, (const __half*)w2_p, b2, ye_p);

    combine_kernel<<<T_TOK, 256>>>(out);
}

// round 9
// speedup vs baseline: 1.0486x; 1.0486x over previous
#include <cuda_runtime.h>
#include <cuda_fp16.h>
#include <cstdint>
#include <math.h>

// Problem constants
#define T_TOK 4096
#define D_DIM 2048
#define FF_DIM 8192
#define E_EXP 16
#define CAP 640          // ceil(1.25 * 2 * 4096 / 16)

// ---------------------------------------------------------------------------
// Scratch (device globals — allocation-free kernel_launch)
// ---------------------------------------------------------------------------
__device__ __half g_W1h[(size_t)E_EXP * D_DIM * FF_DIM];  // W1 fp16 [E][D][FF]
__device__ __half g_W2h[(size_t)E_EXP * FF_DIM * D_DIM];  // W2 fp16 [E][FF][D]
__device__ __half g_Xe [(size_t)E_EXP * CAP * D_DIM];     // dispatched tokens fp16
__device__ __half g_h  [(size_t)E_EXP * CAP * FF_DIM];    // gelu(Xe@W1+b1) fp16
__device__ __half g_Ye [(size_t)E_EXP * CAP * D_DIM];     // expert outputs fp16
__device__ int    g_eidx[T_TOK * 2];
__device__ float  g_gate[T_TOK * 2];
__device__ int    g_pos [T_TOK * 2];

// ---------------------------------------------------------------------------
// Helpers
// ---------------------------------------------------------------------------
__device__ __forceinline__ float gelu_exact(float v) {
    return 0.5f * v * (1.0f + erff(v * 0.70710678118654752f));
}

__device__ __forceinline__ void cp_async16(uint32_t smem_addr, const void* gmem) {
    asm volatile("cp.async.cg.shared.global [%0], [%1], 16;\n" :: "r"(smem_addr), "l"(gmem));
}

__device__ __forceinline__ void ldsm_x4(uint32_t (&r)[4], uint32_t addr) {
    asm volatile("ldmatrix.sync.aligned.m8n8.x4.shared.b16 {%0,%1,%2,%3}, [%4];"
        : "=r"(r[0]), "=r"(r[1]), "=r"(r[2]), "=r"(r[3]) : "r"(addr));
}

__device__ __forceinline__ void ldsm_x4_trans(uint32_t (&r)[4], uint32_t addr) {
    asm volatile("ldmatrix.sync.aligned.m8n8.x4.trans.shared.b16 {%0,%1,%2,%3}, [%4];"
        : "=r"(r[0]), "=r"(r[1]), "=r"(r[2]), "=r"(r[3]) : "r"(addr));
}

__device__ __forceinline__ void mma_f16(float (&c)[4], const uint32_t (&a)[4],
                                        uint32_t b0, uint32_t b1) {
    asm volatile(
        "mma.sync.aligned.m16n8k16.row.col.f32.f16.f16.f32 "
        "{%0,%1,%2,%3}, {%4,%5,%6,%7}, {%8,%9}, {%0,%1,%2,%3};"
        : "+f"(c[0]), "+f"(c[1]), "+f"(c[2]), "+f"(c[3])
        : "r"(a[0]), "r"(a[1]), "r"(a[2]), "r"(a[3]), "r"(b0), "r"(b1));
}

// ---------------------------------------------------------------------------
// 1) Gating: one warp per token (unchanged, proven)
// ---------------------------------------------------------------------------
__global__ void gate_kernel(const float* __restrict__ x, const float* __restrict__ Wg) {
    int t = (blockIdx.x * blockDim.x + threadIdx.x) >> 5;
    int lane = threadIdx.x & 31;
    if (t >= T_TOK) return;
    const float* xr = x + (size_t)t * D_DIM;

    float acc[E_EXP];
#pragma unroll
    for (int e = 0; e < E_EXP; e++) acc[e] = 0.0f;

    for (int d = lane; d < D_DIM; d += 32) {
        float xv = xr[d];
        const float4* wg = (const float4*)(Wg + (size_t)d * E_EXP);
#pragma unroll
        for (int q = 0; q < 4; q++) {
            float4 w = wg[q];
            acc[q * 4 + 0] += xv * w.x;
            acc[q * 4 + 1] += xv * w.y;
            acc[q * 4 + 2] += xv * w.z;
            acc[q * 4 + 3] += xv * w.w;
        }
    }
#pragma unroll
    for (int e = 0; e < E_EXP; e++) {
        float v = acc[e];
#pragma unroll
        for (int o = 16; o > 0; o >>= 1) v += __shfl_xor_sync(0xffffffffu, v, o);
        acc[e] = v;
    }
    if (lane == 0) {
        int i1 = 0; float v1 = acc[0];
#pragma unroll
        for (int e = 1; e < E_EXP; e++) if (acc[e] > v1) { v1 = acc[e]; i1 = e; }
        int i2 = -1; float v2 = -1e30f;
#pragma unroll
        for (int e = 0; e < E_EXP; e++)
            if (e != i1 && acc[e] > v2) { v2 = acc[e]; i2 = e; }
        float r  = expf(v2 - v1);
        float g1 = 1.0f / (1.0f + r);
        float g2 = r * g1;
        g_eidx[t * 2 + 0] = i1;  g_eidx[t * 2 + 1] = i2;
        g_gate[t * 2 + 0] = g1;  g_gate[t * 2 + 1] = g2;
    }
}

// ---------------------------------------------------------------------------
// 2) Ordered capacity scan — PARALLEL (proven in R7)
// ---------------------------------------------------------------------------
__global__ void scan_kernel() {
    const int e = blockIdx.x;
    const int wid = threadIdx.x >> 5, lane = threadIdx.x & 31;
    __shared__ int wcnt[8], wbase[8];
    __shared__ int carry;
    if (threadIdx.x == 0) carry = 0;
    __syncthreads();

#pragma unroll
    for (int s = 0; s < 2; s++) {
        int cnt = 0;
        for (int t0 = wid * 512; t0 < wid * 512 + 512; t0 += 32) {
            bool m = (g_eidx[(t0 + lane) * 2 + s] == e);
            cnt += __popc(__ballot_sync(0xffffffffu, m));
        }
        if (lane == 0) wcnt[wid] = cnt;
        __syncthreads();
        if (threadIdx.x == 0) {
            int r = carry;
#pragma unroll
            for (int w = 0; w < 8; w++) { wbase[w] = r; r += wcnt[w]; }
            carry = r;
        }
        __syncthreads();
        int off = wbase[wid];
        for (int t0 = wid * 512; t0 < wid * 512 + 512; t0 += 32) {
            int t = t0 + lane;
            bool m = (g_eidx[t * 2 + s] == e);
            unsigned mask = __ballot_sync(0xffffffffu, m);
            if (m) g_pos[t * 2 + s] = off + __popc(mask & ((1u << lane) - 1u));
            off += __popc(mask);
        }
        __syncthreads();
    }
}

// ---------------------------------------------------------------------------
// 3) Dispatch: scatter token rows into Xe as fp16 (no memset needed)
// ---------------------------------------------------------------------------
__global__ void dispatch_kernel(const float* __restrict__ x) {
    int t = blockIdx.x;
    const float4* xr = (const float4*)(x + (size_t)t * D_DIM);
#pragma unroll
    for (int k = 0; k < 2; k++) {
        int p = g_pos[t * 2 + k];
        if (p < CAP) {
            int e = g_eidx[t * 2 + k];
            uint2* dst = (uint2*)(g_Xe + ((size_t)e * CAP + p) * D_DIM);
            for (int i = threadIdx.x; i < D_DIM / 4; i += blockDim.x) {
                float4 v = xr[i];
                __half2 a = __floats2half2_rn(v.x, v.y);
                __half2 b = __floats2half2_rn(v.z, v.w);
                uint2 u;
                u.x = *reinterpret_cast<uint32_t*>(&a);
                u.y = *reinterpret_cast<uint32_t*>(&b);
                dst[i] = u;
            }
        }
    }
}

// ---------------------------------------------------------------------------
// 3b) Weight convert fp32 -> fp16, layout preserved
// ---------------------------------------------------------------------------
__global__ void convert_w(const float4* __restrict__ in, uint2* __restrict__ out) {
    size_t i = (size_t)blockIdx.x * blockDim.x + threadIdx.x;
    float4 v = in[i];
    __half2 a = __floats2half2_rn(v.x, v.y);
    __half2 b = __floats2half2_rn(v.z, v.w);
    uint2 u;
    u.x = *reinterpret_cast<uint32_t*>(&a);
    u.y = *reinterpret_cast<uint32_t*>(&b);
    out[i] = u;
}

// ---------------------------------------------------------------------------
// 4) Grouped GEMM, fp16 mma.sync.m16n8k16 + ldmatrix, fp32 accumulate.
//    R7-proven config for BOTH GEMMs: BM=BN=128, BK=64, 256 thr (8 warps,
//    warp 64x32), 3-stage cp.async ring, 2 CTAs/SM. A rows 72 halves (144B),
//    B rows 136 halves (272B) => conflict-free ldmatrix. Smem-staged epilogue.
// ---------------------------------------------------------------------------
#define BK 64
#define SA 72            // halves per A smem row (144 B)
#define SB 136           // halves per B smem row (272 B)
#define A_BYTES (128 * SA * 2)        // 18432
#define B_BYTES (BK * SB * 2)         // 17408
#define STAGE_BYTES (A_BYTES + B_BYTES)
#define GEMM_SMEM (3 * STAGE_BYTES)   // 107520

template<int KDIM, int NDIM, bool DOGELU, bool HALFOUT>
__global__ void __launch_bounds__(256, 2)
gemm_hmma(const __half* __restrict__ A, const __half* __restrict__ Bw,
          const float* __restrict__ bias, void* __restrict__ Cout) {
    constexpr int KT = KDIM / BK;
    extern __shared__ char smem[];
    const uint32_t smem_u32 = (uint32_t)__cvta_generic_to_shared(smem);
    const int tid = threadIdx.x, lane = tid & 31, wid = tid >> 5;
    const int mt = blockIdx.x, nt = blockIdx.y, e = blockIdx.z;
    const int wm = (wid & 1) * 64, wn = (wid >> 1) * 32;

    const __half* Ae = A  + ((size_t)e * CAP + (size_t)mt * 128) * KDIM;
    const __half* Be = Bw + (size_t)e * KDIM * NDIM + (size_t)nt * 128;

    // cp.async slots (4 A chunks + 4 B chunks per thread per stage)
    uint32_t sAoff[4], sBoff[4];
    const __half* gA[4]; const __half* gB[4];
#pragma unroll
    for (int i = 0; i < 4; i++) {
        int u = tid + i * 256;
        int ar = u >> 3, ac = u & 7;           // A: 128 rows x 8 chunks of 8 halves
        sAoff[i] = (ar * SA + ac * 8) * 2;
        gA[i] = Ae + (size_t)ar * KDIM + ac * 8;
        int br = u >> 4, bc = u & 15;          // B: 64 rows x 16 chunks
        sBoff[i] = (uint32_t)A_BYTES + (br * SB + bc * 8) * 2;
        gB[i] = Be + (size_t)br * NDIM + bc * 8;
    }

    // ldmatrix base offsets (bytes, within a stage)
    uint32_t aoff[4], boff[2];
#pragma unroll
    for (int fm = 0; fm < 4; fm++) {
        int row = wm + fm * 16 + (lane & 15);
        int kc  = (lane >> 4) * 8;
        aoff[fm] = (row * SA + kc) * 2;
    }
#pragma unroll
    for (int png = 0; png < 2; png++) {
        int kr = lane & 15;
        int nc = wn + png * 16 + (lane >> 4) * 8;
        boff[png] = (uint32_t)A_BYTES + (kr * SB + nc) * 2;
    }

    float acc[4][4][4];
#pragma unroll
    for (int i = 0; i < 4; i++)
#pragma unroll
        for (int j = 0; j < 4; j++)
#pragma unroll
            for (int q = 0; q < 4; q++) acc[i][j][q] = 0.0f;

    auto load_stage = [&](int s, int kt) {
        uint32_t sb = smem_u32 + s * STAGE_BYTES;
#pragma unroll
        for (int i = 0; i < 4; i++) cp_async16(sb + sAoff[i], gA[i] + kt * BK);
#pragma unroll
        for (int i = 0; i < 4; i++) cp_async16(sb + sBoff[i], gB[i] + (size_t)kt * BK * NDIM);
        asm volatile("cp.async.commit_group;" ::: "memory");
    };

    load_stage(0, 0);
    load_stage(1, 1);

    int s_cur = 0, s_nxt = 2;
    for (int kt = 0; kt < KT; kt++) {
        if (kt + 2 < KT) asm volatile("cp.async.wait_group 1;" ::: "memory");
        else             asm volatile("cp.async.wait_group 0;" ::: "memory");
        __syncthreads();
        if (kt + 2 < KT) load_stage(s_nxt, kt + 2);

        uint32_t sb = smem_u32 + s_cur * STAGE_BYTES;
#pragma unroll
        for (int ks = 0; ks < 4; ks++) {
            uint32_t a[4][4], b[2][4];
#pragma unroll
            for (int fm = 0; fm < 4; fm++)
                ldsm_x4(a[fm], sb + aoff[fm] + ks * 32);            // +16 halves in k
#pragma unroll
            for (int png = 0; png < 2; png++)
                ldsm_x4_trans(b[png], sb + boff[png] + ks * (16 * SB * 2));
#pragma unroll
            for (int fm = 0; fm < 4; fm++)
#pragma unroll
                for (int fn = 0; fn < 4; fn++)
                    mma_f16(acc[fm][fn], a[fm], b[fn >> 1][(fn & 1) * 2],
                            b[fn >> 1][(fn & 1) * 2 + 1]);
        }
        s_cur = (s_cur == 2) ? 0 : s_cur + 1;
        s_nxt = (s_nxt == 2) ? 0 : s_nxt + 1;
    }

    // bias for this warp's columns
    float bias0[4], bias1[4];
#pragma unroll
    for (int fn = 0; fn < 4; fn++) {
        int c = nt * 128 + wn + fn * 8 + (lane & 3) * 2;
        bias0[fn] = __ldg(bias + (size_t)e * NDIM + c);
        bias1[fn] = __ldg(bias + (size_t)e * NDIM + c + 1);
    }

    __syncthreads();   // mainloop smem dead -> reuse as epilogue staging

    if (HALFOUT) {
        __half* buf = (__half*)smem;          // [128][136] halves
#pragma unroll
        for (int fm = 0; fm < 4; fm++) {
#pragma unroll
            for (int fn = 0; fn < 4; fn++) {
                int row = wm + fm * 16 + (lane >> 2);
                int col = wn + fn * 8 + (lane & 3) * 2;
                float v0 = acc[fm][fn][0] + bias0[fn];
                float v1 = acc[fm][fn][1] + bias1[fn];
                float v2 = acc[fm][fn][2] + bias0[fn];
                float v3 = acc[fm][fn][3] + bias1[fn];
                if (DOGELU) {
                    v0 = gelu_exact(v0); v1 = gelu_exact(v1);
                    v2 = gelu_exact(v2); v3 = gelu_exact(v3);
                }
                __half2 p0 = __floats2half2_rn(v0, v1);
                __half2 p1 = __floats2half2_rn(v2, v3);
                *(uint32_t*)(buf + row * 136 + col)       = *reinterpret_cast<uint32_t*>(&p0);
                *(uint32_t*)(buf + (row + 8) * 136 + col) = *reinterpret_cast<uint32_t*>(&p1);
            }
        }
        __syncthreads();
        __half* Ce = (__half*)Cout + ((size_t)e * CAP + (size_t)mt * 128) * NDIM
                   + (size_t)nt * 128;
#pragma unroll
        for (int i = tid; i < 2048; i += 256) {     // 128 rows x 16 uint4
            int rr = i >> 4, cc = i & 15;
            uint4 v = *(const uint4*)(buf + rr * 136 + cc * 8);
            *(uint4*)(Ce + (size_t)rr * NDIM + cc * 8) = v;
        }
    } else {
        float* buf = (float*)smem;            // [128][132] floats
#pragma unroll
        for (int fm = 0; fm < 4; fm++) {
#pragma unroll
            for (int fn = 0; fn < 4; fn++) {
                int row = wm + fm * 16 + (lane >> 2);
                int col = wn + fn * 8 + (lane & 3) * 2;
                float v0 = acc[fm][fn][0] + bias0[fn];
                float v1 = acc[fm][fn][1] + bias1[fn];
                float v2 = acc[fm][fn][2] + bias0[fn];
                float v3 = acc[fm][fn][3] + bias1[fn];
                *(float2*)(buf + row * 132 + col)       = make_float2(v0, v1);
                *(float2*)(buf + (row + 8) * 132 + col) = make_float2(v2, v3);
            }
        }
        __syncthreads();
        float* Ce = (float*)Cout + ((size_t)e * CAP + (size_t)mt * 128) * NDIM
                  + (size_t)nt * 128;
#pragma unroll
        for (int i = tid; i < 4096; i += 256) {     // 128 rows x 32 uint4
            int rr = i >> 5, cc = i & 31;
            uint4 v = *(const uint4*)(buf + rr * 132 + cc * 4);
            *(uint4*)(Ce + (size_t)rr * NDIM + cc * 4) = v;
        }
    }
}

// ---------------------------------------------------------------------------
// 5) Combine: Ye is fp16
// ---------------------------------------------------------------------------
__global__ void combine_kernel(float* __restrict__ out) {
    int t = blockIdx.x;
    int e0 = g_eidx[t * 2 + 0], e1 = g_eidx[t * 2 + 1];
    int p0 = g_pos[t * 2 + 0],  p1 = g_pos[t * 2 + 1];
    float g0 = (p0 < CAP) ? g_gate[t * 2 + 0] : 0.0f;
    float g1 = (p1 < CAP) ? g_gate[t * 2 + 1] : 0.0f;
    p0 = min(p0, CAP - 1);
    p1 = min(p1, CAP - 1);
    const uint2* y0 = (const uint2*)(g_Ye + ((size_t)e0 * CAP + p0) * D_DIM);
    const uint2* y1 = (const uint2*)(g_Ye + ((size_t)e1 * CAP + p1) * D_DIM);
    float4* o = (float4*)(out + (size_t)t * D_DIM);
    for (int i = threadIdx.x; i < D_DIM / 4; i += blockDim.x) {
        uint2 ua = y0[i], ub = y1[i];
        float2 a0 = __half22float2(*reinterpret_cast<__half2*>(&ua.x));
        float2 a1 = __half22float2(*reinterpret_cast<__half2*>(&ua.y));
        float2 b0 = __half22float2(*reinterpret_cast<__half2*>(&ub.x));
        float2 b1 = __half22float2(*reinterpret_cast<__half2*>(&ub.y));
        float4 rv;
        rv.x = g0 * a0.x + g1 * b0.x;
        rv.y = g0 * a0.y + g1 * b0.y;
        rv.z = g0 * a1.x + g1 * b1.x;
        rv.w = g0 * a1.y + g1 * b1.y;
        o[i] = rv;
    }
}

// ---------------------------------------------------------------------------
// kernel_launch — R7 structure: converts forked on s2 (convert W1 overlaps
// gating chain, convert W2 hides under GEMM1); monolithic GEMM launches.
// ---------------------------------------------------------------------------
extern "C" void kernel_launch(void* const* d_in, const int* in_sizes, int n_in,
                              void* d_out, int out_size) {
    const float* x  = (const float*)d_in[0];
    const float* Wg = (const float*)d_in[1];
    const float* W1 = (const float*)d_in[2];
    const float* b1 = (const float*)d_in[3];
    const float* W2 = (const float*)d_in[4];
    const float* b2 = (const float*)d_in[5];
    float* out = (float*)d_out;

    void *xe_p, *h_p, *ye_p, *w1_p, *w2_p;
    cudaGetSymbolAddress(&xe_p, g_Xe);
    cudaGetSymbolAddress(&h_p,  g_h);
    cudaGetSymbolAddress(&ye_p, g_Ye);
    cudaGetSymbolAddress(&w1_p, g_W1h);
    cudaGetSymbolAddress(&w2_p, g_W2h);

    static cudaStream_t s2 = [] {
        cudaStream_t s;
        cudaStreamCreateWithFlags(&s, cudaStreamNonBlocking);
        return s;
    }();
    static cudaEvent_t evStart = [] {
        cudaEvent_t e; cudaEventCreateWithFlags(&e, cudaEventDisableTiming); return e;
    }();
    static cudaEvent_t evW1 = [] {
        cudaEvent_t e; cudaEventCreateWithFlags(&e, cudaEventDisableTiming); return e;
    }();
    static cudaEvent_t evW2 = [] {
        cudaEvent_t e; cudaEventCreateWithFlags(&e, cudaEventDisableTiming); return e;
    }();

    cudaFuncSetAttribute(gemm_hmma<D_DIM, FF_DIM, true,  true>,
                         cudaFuncAttributeMaxDynamicSharedMemorySize, GEMM_SMEM);
    cudaFuncSetAttribute(gemm_hmma<FF_DIM, D_DIM, false, true>,
                         cudaFuncAttributeMaxDynamicSharedMemorySize, GEMM_SMEM);

    // fork: weight conversion on s2
    cudaEventRecord(evStart, 0);
    cudaStreamWaitEvent(s2, evStart, 0);
    const size_t WN = (size_t)E_EXP * D_DIM * FF_DIM;   // elements per weight tensor
    convert_w<<<(unsigned)(WN / 4 / 256), 256, 0, s2>>>((const float4*)W1, (uint2*)w1_p);
    cudaEventRecord(evW1, s2);
    convert_w<<<(unsigned)(WN / 4 / 256), 256, 0, s2>>>((const float4*)W2, (uint2*)w2_p);
    cudaEventRecord(evW2, s2);

    // main stream: gating chain
    gate_kernel<<<T_TOK / 8, 256>>>(x, Wg);
    scan_kernel<<<E_EXP, 256>>>();
    dispatch_kernel<<<T_TOK, 256>>>(x);

    cudaStreamWaitEvent(0, evW1, 0);
    gemm_hmma<D_DIM, FF_DIM, true, true><<<dim3(CAP / 128, FF_DIM / 128, E_EXP),
                                           256, GEMM_SMEM>>>(
        (const __half*)xe_p, (const __half*)w1_p, b1, h_p);

    cudaStreamWaitEvent(0, evW2, 0);
    gemm_hmma<FF_DIM, D_DIM, false, true><<<dim3(CAP / 128, D_DIM / 128, E_EXP),
                                            256, GEMM_SMEM>>>(
        (const __half*)h_p, (const __half*)w2_p, b2, ye_p);

    combine_kernel<<<T_TOK, 256>>>(out);
}